// round 12
// baseline (speedup 1.0000x reference)
#include <cuda_runtime.h>
#include <cuda_fp16.h>

#define NN 100000
#define EE 800000
#define GG 64
#define ASC  0.00390625f   // 2^-8 (exact) asrc fp16 scale
#define ASCI 256.0f        // 2^8

// ---------------- scratch (static device globals; no allocation) ----------------
__device__ __align__(16) float  g_h[NN * 64];
__device__ __align__(16) __half g_asrc[NN * 64];   // asrc * 2^-8
__device__ __align__(16) float  g_adst[NN * 64];
__device__ __align__(16) float  g_S[NN * 64];
__device__ __align__(16) float  g_y[NN * 32];
__device__ __align__(16) float  g_d2[EE];
__device__ __align__(16) float  g_d2s[EE];
__device__ __align__(16) int    g_srcs[EE];
__device__ int   g_deg[NN];
__device__ int   g_rowptr[NN + 1];
__device__ int   g_cursor[NN];
__device__ int   g_bsum[256];
__device__ __align__(16) float g_W3M[8 * 128 * 64];  // tf32-prerounded [W3a ; W2@W3b] per layer
__device__ __align__(16) float g_c2[8 * 64];
// tf32-prerounded weights: [0,66048) W1 (t1 4 layers then t2 4 layers, each 129*64),
// [66048,70144) t2_Win, [70144,72192) Wlin, [72192,76288) t1_Win
__device__ __align__(16) float g_Wc[76288];
__device__ float g_pool[GG * 32];

// ---------------- tf32 helpers ----------------
__device__ __forceinline__ unsigned f2tf(float x) {
    unsigned r; asm("cvt.rna.tf32.f32 %0, %1;" : "=r"(r) : "f"(x)); return r;
}

__device__ __forceinline__ unsigned f2h2c(float a, float b) {
    __half2 h = __floats2half2_rn(fminf(fmaxf(a, -60000.f), 60000.f),
                                  fminf(fmaxf(b, -60000.f), 60000.f));
    return *(unsigned*)&h;
}

__device__ __forceinline__ void mma_tf32(float* c, const unsigned* a, const unsigned* b) {
    asm volatile("mma.sync.aligned.m16n8k8.row.col.f32.tf32.tf32.f32 "
                 "{%0,%1,%2,%3}, {%4,%5,%6,%7}, {%8,%9}, {%0,%1,%2,%3};"
                 : "+f"(c[0]), "+f"(c[1]), "+f"(c[2]), "+f"(c[3])
                 : "r"(a[0]), "r"(a[1]), "r"(a[2]), "r"(a[3]), "r"(b[0]), "r"(b[1]));
}

// ---------------- setup kernels ----------------
__global__ void k_zero() {
    int i = blockIdx.x * 256 + threadIdx.x;
    if (i < NN) { g_deg[i] = 0; g_cursor[i] = 0; }
    if (i < GG * 32) g_pool[i] = 0.f;
    if (i == 0) g_rowptr[NN] = EE;
}

__global__ void k_d2deg(const float* __restrict__ pos, const int* __restrict__ ei) {
    int e = blockIdx.x * 256 + threadIdx.x;
    if (e >= EE) return;
    int s = ei[e], d = ei[EE + e];
    float dx = pos[s * 3 + 0] - pos[d * 3 + 0];
    float dy = pos[s * 3 + 1] - pos[d * 3 + 1];
    float dz = pos[s * 3 + 2] - pos[d * 3 + 2];
    g_d2[e] = dx * dx + dy * dy + dz * dz;
    atomicAdd(&g_deg[d], 1);
}

// Pre-round all GEMM weights to tf32 (identical values to per-tile cvt before)
__global__ void k_prepW(const float* __restrict__ w1a, const float* __restrict__ w1b,
                        const float* __restrict__ win2, const float* __restrict__ wlin,
                        const float* __restrict__ win1) {
    int i = blockIdx.x * 256 + threadIdx.x;
    if (i >= 76288) return;
    float v;
    if (i < 66048) {
        v = (i < 33024) ? w1a[i] : w1b[i - 33024];
    } else if (i < 70144) {
        v = win2[i - 66048];
    } else if (i < 72192) {
        v = wlin[i - 70144];
    } else {
        v = win1[i - 72192];
    }
    g_Wc[i] = __uint_as_float(f2tf(v));
}

__global__ void k_scan1() {
    __shared__ int sm[256];
    int b = blockIdx.x, base = b * 1024;
    int s = 0;
    for (int j = threadIdx.x; j < 1024; j += 256) {
        int i = base + j;
        if (i < NN) s += g_deg[i];
    }
    sm[threadIdx.x] = s; __syncthreads();
    for (int off = 128; off > 0; off >>= 1) {
        if (threadIdx.x < off) sm[threadIdx.x] += sm[threadIdx.x + off];
        __syncthreads();
    }
    if (threadIdx.x == 0) g_bsum[b] = sm[0];
}

__global__ void k_scan2(int nblk) {
    __shared__ int sm[256];
    int t = threadIdx.x;
    if (t < nblk) sm[t] = g_bsum[t];
    __syncthreads();
    if (t == 0) {
        int run = 0;
        for (int i = 0; i < nblk; i++) { int v = sm[i]; sm[i] = run; run += v; }
    }
    __syncthreads();
    if (t < nblk) g_bsum[t] = sm[t];
}

__global__ void k_scan3() {
    __shared__ int sm[1024];
    int b = blockIdx.x, t = threadIdx.x, i = b * 1024 + t;
    int v = (i < NN) ? g_deg[i] : 0;
    sm[t] = v; __syncthreads();
    for (int off = 1; off < 1024; off <<= 1) {
        int x = sm[t];
        if (t >= off) x += sm[t - off];
        __syncthreads(); sm[t] = x; __syncthreads();
    }
    if (i < NN) g_rowptr[i] = g_bsum[b] + sm[t] - v;
}

__global__ void k_scatter(const int* __restrict__ ei) {
    int e = blockIdx.x * 256 + threadIdx.x;
    if (e >= EE) return;
    int d = ei[EE + e];
    int p = g_rowptr[d] + atomicAdd(&g_cursor[d], 1);
    g_srcs[p] = ei[e];
    g_d2s[p] = g_d2[e];
}

// Build per-layer combined update weight (tf32-prerounded): g_W3M = [W3a ; W2@W3b], g_c2 = b2@W3b
__global__ void k_prepM(const float* __restrict__ w2a, const float* __restrict__ w3a,
                        const float* __restrict__ b2a, const float* __restrict__ w2b,
                        const float* __restrict__ w3b, const float* __restrict__ b2b) {
    int b = blockIdx.x; // 0..7
    const float* W2  = (b < 4 ? w2a : w2b) + (b & 3) * 4096;
    const float* W3  = (b < 4 ? w3a : w3b) + (b & 3) * 8192;   // 128x64
    const float* B2  = (b < 4 ? b2a : b2b) + (b & 3) * 64;
    const float* W3B = W3 + 4096;
    __shared__ float s2[4096], s3[4096];
    int t = threadIdx.x;
    for (int j = 0; j < 16; j++) { s2[t + j * 256] = W2[t + j * 256]; s3[t + j * 256] = W3B[t + j * 256]; }
    __syncthreads();
    for (int j = 0; j < 16; j++) {
        int idx = t + j * 256, r = idx >> 6, c = idx & 63;
        float a = 0.f;
        #pragma unroll 8
        for (int k = 0; k < 64; k++) a += s2[r * 64 + k] * s3[k * 64 + c];
        g_W3M[b * 8192 + 4096 + idx] = __uint_as_float(f2tf(a));
        g_W3M[b * 8192 + idx] = __uint_as_float(f2tf(W3[idx]));
    }
    if (t < 64) {
        float a = 0.f;
        for (int k = 0; k < 64; k++) a += B2[k] * s3[k * 64 + t];
        g_c2[b * 64 + t] = a;
    }
}

// ---------------- generic tf32 GEMM (K=64), N split into <=64-col passes ----------------
// W must be tf32-prerounded. ALD: 0 = A[N,64] fp32, 2 = features(pos|emb[z])
// EPI: 0 = store O0 fp32, 2 = proj split: pass0 cols -> asrc fp16 (scaled), pass1 -> adst + bias
template<int CO, int ALD, int EPI>
__global__ void __launch_bounds__(256, 4) k_mma(
    const float* __restrict__ A, const float* __restrict__ W,
    const float* __restrict__ bias, float* __restrict__ O0,
    float* __restrict__ O1, const float* __restrict__ pos,
    const int* __restrict__ z, const float* __restrict__ emb)
{
    extern __shared__ float sm[];
    float* sA = sm;             // 128 x 68
    float* sW = sm + 128 * 68;  // 64 x 68 (n-major), per pass
    const int tid = threadIdx.x;
    const int lane = tid & 31;
    const int wid = tid >> 5;
    const int warpM = wid & 3;
    const int warpN = wid >> 2;
    constexpr int NPASS = (CO + 63) / 64;
    constexpr int CW = (CO < 64) ? CO : 64;
    constexpr int NPW = CW / 2;
    constexpr int NF = NPW / 8;
    const int row0 = blockIdx.x * 128;

    // ---- A tile (tf32) ----
    if (ALD == 2) {
        #pragma unroll
        for (int i = 0; i < 32; i++) {
            int idx = tid + i * 256;
            int r = idx >> 6, c = idx & 63, gr = row0 + r;
            float v = 0.f;
            if (gr < NN) v = (c < 3) ? pos[gr * 3 + c] : emb[z[gr] * 61 + (c - 3)];
            sA[r * 68 + c] = __uint_as_float(f2tf(v));
        }
    } else {
        #pragma unroll
        for (int i = 0; i < 8; i++) {
            int idx = tid + i * 256;
            int r = idx >> 4, c4 = idx & 15, gr = row0 + r;
            float4 v = make_float4(0.f, 0.f, 0.f, 0.f);
            if (gr < NN) v = ((const float4*)A)[gr * 16 + c4];
            uint4 u = make_uint4(f2tf(v.x), f2tf(v.y), f2tf(v.z), f2tf(v.w));
            *(uint4*)&sA[r * 68 + c4 * 4] = u;
        }
    }

    const int lr = lane >> 2, lc = lane & 3, lc2 = (lane & 3) * 2;

    #pragma unroll
    for (int nh = 0; nh < NPASS; nh++) {
        // ---- W slice (n-major, already tf32) ----
        #pragma unroll
        for (int i = 0; i < (CW * 64) / 256; i++) {
            int idx = tid + i * 256;
            int k = idx / CW, c = idx % CW;
            float w;
            if (EPI == 2) w = W[(nh * 64 + k) * 64 + c];   // [129][64] stacked W1a/W1b
            else          w = W[k * CO + (nh * 64 + c)];
            sW[c * 68 + k] = w;
        }
        __syncthreads();

        float cc[2][NF][4];
        #pragma unroll
        for (int mt = 0; mt < 2; mt++)
            #pragma unroll
            for (int j = 0; j < NF; j++)
                cc[mt][j][0] = cc[mt][j][1] = cc[mt][j][2] = cc[mt][j][3] = 0.f;

        #pragma unroll
        for (int k0 = 0; k0 < 64; k0 += 8) {
            unsigned a[2][4];
            #pragma unroll
            for (int mt = 0; mt < 2; mt++) {
                int r = warpM * 32 + mt * 16 + lr;
                a[mt][0] = __float_as_uint(sA[r * 68 + k0 + lc]);
                a[mt][1] = __float_as_uint(sA[(r + 8) * 68 + k0 + lc]);
                a[mt][2] = __float_as_uint(sA[r * 68 + k0 + lc + 4]);
                a[mt][3] = __float_as_uint(sA[(r + 8) * 68 + k0 + lc + 4]);
            }
            unsigned b[NF][2];
            #pragma unroll
            for (int j = 0; j < NF; j++) {
                int n = warpN * NPW + j * 8 + lr;
                b[j][0] = __float_as_uint(sW[n * 68 + k0 + lc]);
                b[j][1] = __float_as_uint(sW[n * 68 + k0 + 4 + lc]);
            }
            #pragma unroll
            for (int mt = 0; mt < 2; mt++)
                #pragma unroll
                for (int j = 0; j < NF; j++)
                    mma_tf32(cc[mt][j], a[mt], b[j]);
        }

        // ---- epilogue for this pass ----
        #pragma unroll
        for (int mt = 0; mt < 2; mt++) {
            #pragma unroll
            for (int j = 0; j < NF; j++) {
                int col = nh * 64 + warpN * NPW + j * 8 + lc2;
                #pragma unroll
                for (int half = 0; half < 2; half++) {
                    int r = row0 + warpM * 32 + mt * 16 + lr + half * 8;
                    if (r >= NN) continue;
                    float v0 = cc[mt][j][half * 2 + 0];
                    float v1 = cc[mt][j][half * 2 + 1];
                    if (EPI == 0) {
                        ((float2*)O0)[(r * CO + col) >> 1] = make_float2(v0, v1);
                    } else { // EPI == 2
                        if (col < 64) {
                            *(unsigned*)&((__half*)O0)[r * 64 + col] =
                                f2h2c(v0 * ASC, v1 * ASC);
                        } else {
                            int sc = col - 64;
                            ((float2*)O1)[(r * 64 + sc) >> 1] =
                                make_float2(v0 + bias[sc], v1 + bias[sc + 1]);
                        }
                    }
                }
            }
        }
        if (nh + 1 < NPASS) __syncthreads();
    }
}

// ---------------- standalone edge aggregation (fp16 asrc in, fp32 S out) ----------------
__global__ void __launch_bounds__(256) k_agg(const float* __restrict__ wd) {
    int gt = blockIdx.x * 256 + threadIdx.x;
    int n = gt >> 5, lane = gt & 31;
    if (n >= NN) return;
    const __half2* asrc2 = (const __half2*)g_asrc;
    float2 ad = ((const float2*)g_adst)[n * 32 + lane];
    float2 wdv = ((const float2*)wd)[lane];
    ad.x *= ASC; ad.y *= ASC;
    wdv.x *= ASC; wdv.y *= ASC;
    float ax = 0.f, ay = 0.f;
    int e0 = g_rowptr[n], e1 = g_rowptr[n + 1];
    int e = e0;
    while (e < e1) {
        int cnt = e1 - e; if (cnt > 8) cnt = 8;
        int sa[8]; float da[8];
        #pragma unroll
        for (int j = 0; j < 8; j++) if (j < cnt) { sa[j] = g_srcs[e + j]; da[j] = g_d2s[e + j]; }
        #pragma unroll
        for (int j = 0; j < 8; j++) if (j < cnt) {
            float2 af = __half22float2(asrc2[sa[j] * 32 + lane]);
            float px = af.x + ad.x + da[j] * wdv.x;
            float py = af.y + ad.y + da[j] * wdv.y;
            ax += fmaxf(px, 0.f); ay += fmaxf(py, 0.f);
        }
        e += cnt;
    }
    ((float2*)g_S)[n * 32 + lane] = make_float2(ax * ASCI, ay * ASCI);
}

// ---------------- fused node-update + next projection (K-split phase1, N-split phase2) ----------------
// W (g_W3M) and W2 must be tf32-prerounded.
// Phase 1: hnew = h + relu([h|S] @ W3M + deg*c2 + b3)  (two K=64 passes over shared A buffer)
// Phase 2 (MODE 0): [asrc|adst] = hnew @ [W1a|W1b] (+b1)   (two 64-col passes)
// Phase 2 (MODE 1): hio = relu(hnew) @ W2                  (one pass)
// Phase 2 (MODE 2): yO = relu(hnew) @ W2 + bias2           (one 32-col pass)
template<int CO2, int MODE>
__global__ void __launch_bounds__(256, 4) k_updproj(
    const float* __restrict__ W, const float* __restrict__ c2v,
    const float* __restrict__ b3v, const float* __restrict__ W2,
    const float* __restrict__ bias2, float* __restrict__ hio,
    __half* __restrict__ asrcO, float* __restrict__ adstO,
    float* __restrict__ yO)
{
    extern __shared__ float sm[];
    float* sA = sm;             // 128 x 68
    float* sW = sm + 128 * 68;  // 64 x 68 n-major
    const int tid = threadIdx.x;
    const int lane = tid & 31;
    const int wid = tid >> 5;
    const int warpM = wid & 3;
    const int warpN = wid >> 2;
    const int row0 = blockIdx.x * 128;
    const int lr = lane >> 2, lc = lane & 3, lc2 = (lane & 3) * 2;

    float cc[2][4][4];
    #pragma unroll
    for (int mt = 0; mt < 2; mt++)
        #pragma unroll
        for (int j = 0; j < 4; j++)
            cc[mt][j][0] = cc[mt][j][1] = cc[mt][j][2] = cc[mt][j][3] = 0.f;

    // ---- phase-1: two K=64 passes (kp=0: h, kp=1: S) ----
    #pragma unroll
    for (int kp = 0; kp < 2; kp++) {
        const float* Asrc = (kp == 0) ? hio : (const float*)g_S;
        #pragma unroll
        for (int i = 0; i < 8; i++) {
            int idx = tid + i * 256;
            int r = idx >> 4, c4 = idx & 15, gr = row0 + r;
            float4 v = make_float4(0.f, 0.f, 0.f, 0.f);
            if (gr < NN) v = ((const float4*)Asrc)[gr * 16 + c4];
            uint4 u = make_uint4(f2tf(v.x), f2tf(v.y), f2tf(v.z), f2tf(v.w));
            *(uint4*)&sA[r * 68 + c4 * 4] = u;
        }
        #pragma unroll
        for (int i = 0; i < 16; i++) {
            int idx = tid + i * 256;
            int kk = idx >> 6, c = idx & 63;
            sW[c * 68 + kk] = W[(kp * 64 + kk) * 64 + c];
        }
        __syncthreads();

        #pragma unroll
        for (int k0 = 0; k0 < 64; k0 += 8) {
            unsigned a[2][4];
            #pragma unroll
            for (int mt = 0; mt < 2; mt++) {
                int r = warpM * 32 + mt * 16 + lr;
                a[mt][0] = __float_as_uint(sA[r * 68 + k0 + lc]);
                a[mt][1] = __float_as_uint(sA[(r + 8) * 68 + k0 + lc]);
                a[mt][2] = __float_as_uint(sA[r * 68 + k0 + lc + 4]);
                a[mt][3] = __float_as_uint(sA[(r + 8) * 68 + k0 + lc + 4]);
            }
            unsigned b[4][2];
            #pragma unroll
            for (int j = 0; j < 4; j++) {
                int n = warpN * 32 + j * 8 + lr;
                b[j][0] = __float_as_uint(sW[n * 68 + k0 + lc]);
                b[j][1] = __float_as_uint(sW[n * 68 + k0 + 4 + lc]);
            }
            #pragma unroll
            for (int mt = 0; mt < 2; mt++)
                #pragma unroll
                for (int j = 0; j < 4; j++)
                    mma_tf32(cc[mt][j], a[mt], b[j]);
        }
        __syncthreads();
    }

    // ---- preload phase-2 W pass 0 (sW free) ----
    constexpr int NPASS2 = (CO2 + 63) / 64;
    constexpr int CW2 = (CO2 < 64) ? CO2 : 64;
    constexpr int NPW2 = CW2 / 2;
    constexpr int NF2 = NPW2 / 8;
    #pragma unroll
    for (int i = 0; i < (CW2 * 64) / 256; i++) {
        int idx = tid + i * 256;
        int kk = idx / CW2, c = idx % CW2;
        float w;
        if (MODE == 0) w = W2[kk * 64 + c];          // pass 0 = W1a
        else           w = W2[kk * CO2 + c];
        sW[c * 68 + kk] = w;
    }

    // ---- phase-1 epilogue: hnew -> (global h for MODE0) + sA cols 0-63 ----
    #pragma unroll
    for (int mt = 0; mt < 2; mt++) {
        #pragma unroll
        for (int j = 0; j < 4; j++) {
            int col = warpN * 32 + j * 8 + lc2;
            #pragma unroll
            for (int half = 0; half < 2; half++) {
                int rl = warpM * 32 + mt * 16 + lr + half * 8;
                int r = row0 + rl;
                if (r >= NN) continue;   // rows >= NN keep zeros (S pass zeroed them)
                float v0 = cc[mt][j][half * 2 + 0];
                float v1 = cc[mt][j][half * 2 + 1];
                float2 hv = ((const float2*)hio)[(r * 64 + col) >> 1];
                float dg = (float)g_deg[r];
                float o0 = hv.x + fmaxf(v0 + dg * c2v[col] + b3v[col], 0.f);
                float o1 = hv.y + fmaxf(v1 + dg * c2v[col + 1] + b3v[col + 1], 0.f);
                if (MODE == 0)
                    ((float2*)hio)[(r * 64 + col) >> 1] = make_float2(o0, o1);
                float a0 = (MODE != 0) ? fmaxf(o0, 0.f) : o0;
                float a1 = (MODE != 0) ? fmaxf(o1, 0.f) : o1;
                sA[rl * 68 + col]     = __uint_as_float(f2tf(a0));
                sA[rl * 68 + col + 1] = __uint_as_float(f2tf(a1));
            }
        }
    }
    __syncthreads();

    // ---- phase-2: N passes ----
    #pragma unroll
    for (int nh = 0; nh < NPASS2; nh++) {
        if (nh > 0) {
            __syncthreads();
            #pragma unroll
            for (int i = 0; i < (CW2 * 64) / 256; i++) {
                int idx = tid + i * 256;
                int kk = idx / CW2, c = idx % CW2;
                sW[c * 68 + kk] = W2[(64 + kk) * 64 + c];  // pass 1 = W1b
            }
            __syncthreads();
        }

        float dd[2][NF2][4];
        #pragma unroll
        for (int mt = 0; mt < 2; mt++)
            #pragma unroll
            for (int j = 0; j < NF2; j++)
                dd[mt][j][0] = dd[mt][j][1] = dd[mt][j][2] = dd[mt][j][3] = 0.f;

        #pragma unroll
        for (int k0 = 0; k0 < 64; k0 += 8) {
            unsigned a[2][4];
            #pragma unroll
            for (int mt = 0; mt < 2; mt++) {
                int r = warpM * 32 + mt * 16 + lr;
                a[mt][0] = __float_as_uint(sA[r * 68 + k0 + lc]);
                a[mt][1] = __float_as_uint(sA[(r + 8) * 68 + k0 + lc]);
                a[mt][2] = __float_as_uint(sA[r * 68 + k0 + lc + 4]);
                a[mt][3] = __float_as_uint(sA[(r + 8) * 68 + k0 + lc + 4]);
            }
            unsigned b[NF2][2];
            #pragma unroll
            for (int j = 0; j < NF2; j++) {
                int n = warpN * NPW2 + j * 8 + lr;
                b[j][0] = __float_as_uint(sW[n * 68 + k0 + lc]);
                b[j][1] = __float_as_uint(sW[n * 68 + k0 + 4 + lc]);
            }
            #pragma unroll
            for (int mt = 0; mt < 2; mt++)
                #pragma unroll
                for (int j = 0; j < NF2; j++)
                    mma_tf32(dd[mt][j], a[mt], b[j]);
        }

        #pragma unroll
        for (int mt = 0; mt < 2; mt++) {
            #pragma unroll
            for (int j = 0; j < NF2; j++) {
                int col = nh * 64 + warpN * NPW2 + j * 8 + lc2;
                #pragma unroll
                for (int half = 0; half < 2; half++) {
                    int r = row0 + warpM * 32 + mt * 16 + lr + half * 8;
                    if (r >= NN) continue;
                    float v0 = dd[mt][j][half * 2 + 0];
                    float v1 = dd[mt][j][half * 2 + 1];
                    if (MODE == 0) {
                        if (col < 64) {
                            *(unsigned*)&asrcO[r * 64 + col] = f2h2c(v0 * ASC, v1 * ASC);
                        } else {
                            int sc = col - 64;
                            ((float2*)adstO)[(r * 64 + sc) >> 1] =
                                make_float2(v0 + bias2[sc], v1 + bias2[sc + 1]);
                        }
                    } else if (MODE == 1) {
                        ((float2*)hio)[(r * 64 + col) >> 1] = make_float2(v0, v1);
                    } else {
                        ((float2*)yO)[(r * 32 + col) >> 1] =
                            make_float2(v0 + bias2[col], v1 + bias2[col + 1]);
                    }
                }
            }
        }
    }
}

// ---------------- pooling ----------------
__global__ void k_pool_acc(const int* __restrict__ batch) {
    int gt = blockIdx.x * 256 + threadIdx.x;
    int w = gt >> 5, lane = gt & 31;
    const int TW = 64 * 8;
    const int STRIP = (NN + TW - 1) / TW;
    int n0 = w * STRIP;
    if (n0 >= NN) return;
    int n1 = n0 + STRIP; if (n1 > NN) n1 = NN;
    int cur = batch[n0]; float acc = 0.f;
    for (int n = n0; n < n1; n++) {
        int g = batch[n];
        float v = g_y[n * 32 + lane];
        if (g != cur) { atomicAdd(&g_pool[cur * 32 + lane], acc); acc = 0.f; cur = g; }
        acc += v;
    }
    atomicAdd(&g_pool[cur * 32 + lane], acc);
}

__global__ void k_pool_fin(const int* __restrict__ batch, float* __restrict__ out) {
    int i = blockIdx.x * 256 + threadIdx.x;
    if (i >= GG * 32) return;
    int g = i >> 5;
    int lo = 0, hi = NN;
    while (lo < hi) { int mid = (lo + hi) >> 1; if (batch[mid] < g) lo = mid + 1; else hi = mid; }
    int a = lo;
    lo = 0; hi = NN;
    while (lo < hi) { int mid = (lo + hi) >> 1; if (batch[mid] < g + 1) lo = mid + 1; else hi = mid; }
    int cnt = lo - a;
    out[i] = g_pool[i] / fmaxf((float)cnt, 1.f);
}

// ---------------- launch ----------------
extern "C" void kernel_launch(void* const* d_in, const int* in_sizes, int n_in,
                              void* d_out, int out_size) {
    const float* pos    = (const float*)d_in[0];
    const int*   z      = (const int*)d_in[1];
    const int*   ei     = (const int*)d_in[2];
    const int*   batch  = (const int*)d_in[3];
    const float* emb    = (const float*)d_in[4];
    const float* t1_Win = (const float*)d_in[5];
    const float* t1_W1  = (const float*)d_in[6];
    const float* t1_b1  = (const float*)d_in[7];
    const float* t1_W2  = (const float*)d_in[8];
    const float* t1_b2  = (const float*)d_in[9];
    const float* t1_W3  = (const float*)d_in[10];
    const float* t1_b3  = (const float*)d_in[11];
    const float* t2_Win = (const float*)d_in[12];
    const float* t2_W1  = (const float*)d_in[13];
    const float* t2_b1  = (const float*)d_in[14];
    const float* t2_W2  = (const float*)d_in[15];
    const float* t2_b2  = (const float*)d_in[16];
    const float* t2_W3  = (const float*)d_in[17];
    const float* t2_b3  = (const float*)d_in[18];
    const float* Wlin   = (const float*)d_in[19];
    const float* blin   = (const float*)d_in[20];
    float* out = (float*)d_out;

    float *ph, *pad, *py, *pW3M, *pc2, *pWc;
    __half* pash;
    cudaGetSymbolAddress((void**)&ph, g_h);
    cudaGetSymbolAddress((void**)&pash, g_asrc);
    cudaGetSymbolAddress((void**)&pad, g_adst);
    cudaGetSymbolAddress((void**)&py, g_y);
    cudaGetSymbolAddress((void**)&pW3M, g_W3M);
    cudaGetSymbolAddress((void**)&pc2, g_c2);
    cudaGetSymbolAddress((void**)&pWc, g_Wc);

    const int NB = (NN + 127) / 128;
    const int nscan = (NN + 1023) / 1024;
    const int SM_T = (128 * 68 + 64 * 68) * 4;   // 52224 for all GEMM kernels

    cudaFuncSetAttribute(k_mma<64, 2, 0>,   cudaFuncAttributeMaxDynamicSharedMemorySize, SM_T);
    cudaFuncSetAttribute(k_mma<128, 0, 2>,  cudaFuncAttributeMaxDynamicSharedMemorySize, SM_T);
    cudaFuncSetAttribute(k_updproj<128, 0>, cudaFuncAttributeMaxDynamicSharedMemorySize, SM_T);
    cudaFuncSetAttribute(k_updproj<64, 1>,  cudaFuncAttributeMaxDynamicSharedMemorySize, SM_T);
    cudaFuncSetAttribute(k_updproj<32, 2>,  cudaFuncAttributeMaxDynamicSharedMemorySize, SM_T);

    // pre-rounded weight views
    const float* cW1t1  = pWc;                 // t1 W1 (4 layers x 129x64)
    const float* cW1t2  = pWc + 33024;         // t2 W1
    const float* cWin2  = pWc + 66048;         // t2_Win 64x64
    const float* cWlin  = pWc + 70144;         // Wlin 64x32
    const float* cWin1  = pWc + 72192;         // t1_Win 64x64

    // setup (prepW before first GEMM; proj stays launch #6 for ncu)
    k_zero<<<(NN + 255) / 256, 256>>>();
    k_d2deg<<<(EE + 255) / 256, 256>>>(pos, ei);
    k_prepW<<<(76288 + 255) / 256, 256>>>(t1_W1, t2_W1, t2_Win, Wlin, t1_Win);
    // features + input projection  h = [pos|emb[z]] @ t1_Win
    k_mma<64, 2, 0><<<NB, 256, SM_T>>>(
        nullptr, cWin1, nullptr, ph, nullptr, pos, z, emb);
    k_scan1<<<nscan, 256>>>();
    // t1 layer-0 projection (profiled launch)
    k_mma<128, 0, 2><<<NB, 256, SM_T>>>(
        ph, cW1t1, t1_b1, (float*)pash, pad, nullptr, nullptr, nullptr);
    // CSR build + weight prep
    k_scan2<<<1, 128>>>(nscan);
    k_scan3<<<nscan, 1024>>>();
    k_scatter<<<(EE + 255) / 256, 256>>>(ei);
    k_prepM<<<8, 256>>>(t1_W2, t1_W3, t1_b2, t2_W2, t2_W3, t2_b2);

    for (int t = 0; t < 2; t++) {
        const float* W1raw = (t == 0 ? t1_W1 : t2_W1);     // for agg wd column (fp32)
        const float* cW1   = (t == 0 ? cW1t1 : cW1t2);
        const float* b1 = (t == 0 ? t1_b1 : t2_b1);
        const float* b3 = (t == 0 ? t1_b3 : t2_b3);
        for (int l = 0; l < 4; l++) {
            k_agg<<<(NN * 32 + 255) / 256, 256>>>(W1raw + l * 129 * 64 + 128 * 64);
            const float* Wu = pW3M + (t * 4 + l) * 8192;
            const float* cu = pc2 + (t * 4 + l) * 64;
            if (l < 3) {
                k_updproj<128, 0><<<NB, 256, SM_T>>>(
                    Wu, cu, b3 + l * 64, cW1 + (l + 1) * 129 * 64, b1 + (l + 1) * 64,
                    ph, pash, pad, nullptr);
            } else if (t == 0) {
                k_updproj<64, 1><<<NB, 256, SM_T>>>(
                    Wu, cu, b3 + l * 64, cWin2, nullptr,
                    ph, nullptr, nullptr, nullptr);
            } else {
                k_updproj<32, 2><<<NB, 256, SM_T>>>(
                    Wu, cu, b3 + l * 64, cWlin, blin,
                    ph, nullptr, nullptr, py);
            }
        }
        if (t == 0) {
            k_mma<128, 0, 2><<<NB, 256, SM_T>>>(
                ph, cW1t2, t2_b1, (float*)pash, pad, nullptr, nullptr, nullptr);
        }
    }
    k_pool_acc<<<64, 256>>>(batch);
    k_pool_fin<<<(GG * 32 + 255) / 256, 256>>>(batch, out);
}

// round 15
// speedup vs baseline: 1.0876x; 1.0876x over previous
#include <cuda_runtime.h>
#include <cuda_fp16.h>

#define NN 100000
#define EE 800000
#define GG 64
#define ASC  0.00390625f   // 2^-8 (exact) asrc fp16 scale
#define ASCI 256.0f        // 2^8

// ---------------- scratch (static device globals; no allocation) ----------------
__device__ __align__(16) float  g_h[NN * 64];
__device__ __align__(16) __half g_asrc[NN * 64];   // asrc * 2^-8
__device__ __align__(16) float  g_adst[NN * 64];
__device__ __align__(16) float  g_S[NN * 64];
__device__ __align__(16) float  g_y[NN * 32];
__device__ __align__(16) float  g_d2[EE];
__device__ __align__(16) float  g_d2s[EE];
__device__ __align__(16) int    g_srcs[EE];
__device__ int   g_deg[NN];
__device__ int   g_rowptr[NN + 1];
__device__ int   g_cursor[NN];
__device__ int   g_bsum[256];
__device__ __align__(16) float g_W3M[8 * 128 * 64];  // tf32-prerounded [W3a ; W2@W3b] per layer
__device__ __align__(16) float g_c2[8 * 64];
// tf32-prerounded weights: [0,66048) W1 (t1 then t2, each 4x129x64),
// [66048,70144) t2_Win, [70144,72192) Wlin, [72192,76288) t1_Win
__device__ __align__(16) float g_Wc[76288];
__device__ float g_pool[GG * 32];

// ---------------- tf32 helpers ----------------
__device__ __forceinline__ unsigned f2tf(float x) {
    unsigned r; asm("cvt.rna.tf32.f32 %0, %1;" : "=r"(r) : "f"(x)); return r;
}

__device__ __forceinline__ unsigned f2h2c(float a, float b) {
    __half2 h = __floats2half2_rn(fminf(fmaxf(a, -60000.f), 60000.f),
                                  fminf(fmaxf(b, -60000.f), 60000.f));
    return *(unsigned*)&h;
}

__device__ __forceinline__ void mma_tf32(float* c, const unsigned* a, const unsigned* b) {
    asm volatile("mma.sync.aligned.m16n8k8.row.col.f32.tf32.tf32.f32 "
                 "{%0,%1,%2,%3}, {%4,%5,%6,%7}, {%8,%9}, {%0,%1,%2,%3};"
                 : "+f"(c[0]), "+f"(c[1]), "+f"(c[2]), "+f"(c[3])
                 : "r"(a[0]), "r"(a[1]), "r"(a[2]), "r"(a[3]), "r"(b[0]), "r"(b[1]));
}

// ---------------- setup kernels ----------------
__global__ void k_zero() {
    int i = blockIdx.x * 256 + threadIdx.x;
    if (i < NN) { g_deg[i] = 0; g_cursor[i] = 0; }
    if (i < GG * 32) g_pool[i] = 0.f;
    if (i == 0) g_rowptr[NN] = EE;
}

__global__ void k_d2deg(const float* __restrict__ pos, const int* __restrict__ ei) {
    int e = blockIdx.x * 256 + threadIdx.x;
    if (e >= EE) return;
    int s = ei[e], d = ei[EE + e];
    float dx = pos[s * 3 + 0] - pos[d * 3 + 0];
    float dy = pos[s * 3 + 1] - pos[d * 3 + 1];
    float dz = pos[s * 3 + 2] - pos[d * 3 + 2];
    g_d2[e] = dx * dx + dy * dy + dz * dz;
    atomicAdd(&g_deg[d], 1);
}

// Pre-round all GEMM weights to tf32 (identical values to per-tile cvt)
__global__ void k_prepW(const float* __restrict__ w1a, const float* __restrict__ w1b,
                        const float* __restrict__ win2, const float* __restrict__ wlin,
                        const float* __restrict__ win1) {
    int i = blockIdx.x * 256 + threadIdx.x;
    if (i >= 76288) return;
    float v;
    if (i < 66048) {
        v = (i < 33024) ? w1a[i] : w1b[i - 33024];
    } else if (i < 70144) {
        v = win2[i - 66048];
    } else if (i < 72192) {
        v = wlin[i - 70144];
    } else {
        v = win1[i - 72192];
    }
    g_Wc[i] = __uint_as_float(f2tf(v));
}

__global__ void k_scan1() {
    __shared__ int sm[256];
    int b = blockIdx.x, base = b * 1024;
    int s = 0;
    for (int j = threadIdx.x; j < 1024; j += 256) {
        int i = base + j;
        if (i < NN) s += g_deg[i];
    }
    sm[threadIdx.x] = s; __syncthreads();
    for (int off = 128; off > 0; off >>= 1) {
        if (threadIdx.x < off) sm[threadIdx.x] += sm[threadIdx.x + off];
        __syncthreads();
    }
    if (threadIdx.x == 0) g_bsum[b] = sm[0];
}

__global__ void k_scan2(int nblk) {
    __shared__ int sm[256];
    int t = threadIdx.x;
    if (t < nblk) sm[t] = g_bsum[t];
    __syncthreads();
    if (t == 0) {
        int run = 0;
        for (int i = 0; i < nblk; i++) { int v = sm[i]; sm[i] = run; run += v; }
    }
    __syncthreads();
    if (t < nblk) g_bsum[t] = sm[t];
}

__global__ void k_scan3() {
    __shared__ int sm[1024];
    int b = blockIdx.x, t = threadIdx.x, i = b * 1024 + t;
    int v = (i < NN) ? g_deg[i] : 0;
    sm[t] = v; __syncthreads();
    for (int off = 1; off < 1024; off <<= 1) {
        int x = sm[t];
        if (t >= off) x += sm[t - off];
        __syncthreads(); sm[t] = x; __syncthreads();
    }
    if (i < NN) g_rowptr[i] = g_bsum[b] + sm[t] - v;
}

__global__ void k_scatter(const int* __restrict__ ei) {
    int e = blockIdx.x * 256 + threadIdx.x;
    if (e >= EE) return;
    int d = ei[EE + e];
    int p = g_rowptr[d] + atomicAdd(&g_cursor[d], 1);
    g_srcs[p] = ei[e];
    g_d2s[p] = g_d2[e];
}

// Build per-layer combined update weight (tf32-prerounded): g_W3M = [W3a ; W2@W3b], g_c2 = b2@W3b
__global__ void k_prepM(const float* __restrict__ w2a, const float* __restrict__ w3a,
                        const float* __restrict__ b2a, const float* __restrict__ w2b,
                        const float* __restrict__ w3b, const float* __restrict__ b2b) {
    int b = blockIdx.x; // 0..7
    const float* W2  = (b < 4 ? w2a : w2b) + (b & 3) * 4096;
    const float* W3  = (b < 4 ? w3a : w3b) + (b & 3) * 8192;   // 128x64
    const float* B2  = (b < 4 ? b2a : b2b) + (b & 3) * 64;
    const float* W3B = W3 + 4096;
    __shared__ float s2[4096], s3[4096];
    int t = threadIdx.x;
    for (int j = 0; j < 16; j++) { s2[t + j * 256] = W2[t + j * 256]; s3[t + j * 256] = W3B[t + j * 256]; }
    __syncthreads();
    for (int j = 0; j < 16; j++) {
        int idx = t + j * 256, r = idx >> 6, c = idx & 63;
        float a = 0.f;
        #pragma unroll 8
        for (int k = 0; k < 64; k++) a += s2[r * 64 + k] * s3[k * 64 + c];
        g_W3M[b * 8192 + 4096 + idx] = __uint_as_float(f2tf(a));
        g_W3M[b * 8192 + idx] = __uint_as_float(f2tf(W3[idx]));
    }
    if (t < 64) {
        float a = 0.f;
        for (int k = 0; k < 64; k++) a += B2[k] * s3[k * 64 + t];
        g_c2[b * 64 + t] = a;
    }
}

// ---------------- generic tf32 GEMM (K=64), N split into <=64-col passes ----------------
// W must be tf32-prerounded. ALD: 0 = A[N,64] fp32, 2 = features(pos|emb[z])
// EPI: 0 = store O0 fp32, 2 = proj split: pass0 cols -> asrc fp16 (scaled), pass1 -> adst + bias
template<int CO, int ALD, int EPI>
__global__ void __launch_bounds__(256, 3) k_mma(
    const float* __restrict__ A, const float* __restrict__ W,
    const float* __restrict__ bias, float* __restrict__ O0,
    float* __restrict__ O1, const float* __restrict__ pos,
    const int* __restrict__ z, const float* __restrict__ emb)
{
    extern __shared__ float sm[];
    float* sA = sm;             // 128 x 68
    float* sW = sm + 128 * 68;  // 64 x 68 (n-major), per pass
    const int tid = threadIdx.x;
    const int lane = tid & 31;
    const int wid = tid >> 5;
    const int warpM = wid & 3;
    const int warpN = wid >> 2;
    constexpr int NPASS = (CO + 63) / 64;
    constexpr int CW = (CO < 64) ? CO : 64;
    constexpr int NPW = CW / 2;
    constexpr int NF = NPW / 8;
    const int row0 = blockIdx.x * 128;

    // ---- A tile (tf32) ----
    if (ALD == 2) {
        #pragma unroll
        for (int i = 0; i < 32; i++) {
            int idx = tid + i * 256;
            int r = idx >> 6, c = idx & 63, gr = row0 + r;
            float v = 0.f;
            if (gr < NN) v = (c < 3) ? pos[gr * 3 + c] : emb[z[gr] * 61 + (c - 3)];
            sA[r * 68 + c] = __uint_as_float(f2tf(v));
        }
    } else {
        #pragma unroll
        for (int i = 0; i < 8; i++) {
            int idx = tid + i * 256;
            int r = idx >> 4, c4 = idx & 15, gr = row0 + r;
            float4 v = make_float4(0.f, 0.f, 0.f, 0.f);
            if (gr < NN) v = ((const float4*)A)[gr * 16 + c4];
            uint4 u = make_uint4(f2tf(v.x), f2tf(v.y), f2tf(v.z), f2tf(v.w));
            *(uint4*)&sA[r * 68 + c4 * 4] = u;
        }
    }

    const int lr = lane >> 2, lc = lane & 3, lc2 = (lane & 3) * 2;

    #pragma unroll
    for (int nh = 0; nh < NPASS; nh++) {
        // ---- W slice (n-major, already tf32) ----
        #pragma unroll
        for (int i = 0; i < (CW * 64) / 256; i++) {
            int idx = tid + i * 256;
            int k = idx / CW, c = idx % CW;
            float w;
            if (EPI == 2) w = W[(nh * 64 + k) * 64 + c];   // [129][64] stacked W1a/W1b
            else          w = W[k * CO + (nh * 64 + c)];
            sW[c * 68 + k] = w;
        }
        __syncthreads();

        float cc[2][NF][4];
        #pragma unroll
        for (int mt = 0; mt < 2; mt++)
            #pragma unroll
            for (int j = 0; j < NF; j++)
                cc[mt][j][0] = cc[mt][j][1] = cc[mt][j][2] = cc[mt][j][3] = 0.f;

        #pragma unroll
        for (int k0 = 0; k0 < 64; k0 += 8) {
            unsigned a[2][4];
            #pragma unroll
            for (int mt = 0; mt < 2; mt++) {
                int r = warpM * 32 + mt * 16 + lr;
                a[mt][0] = __float_as_uint(sA[r * 68 + k0 + lc]);
                a[mt][1] = __float_as_uint(sA[(r + 8) * 68 + k0 + lc]);
                a[mt][2] = __float_as_uint(sA[r * 68 + k0 + lc + 4]);
                a[mt][3] = __float_as_uint(sA[(r + 8) * 68 + k0 + lc + 4]);
            }
            unsigned b[NF][2];
            #pragma unroll
            for (int j = 0; j < NF; j++) {
                int n = warpN * NPW + j * 8 + lr;
                b[j][0] = __float_as_uint(sW[n * 68 + k0 + lc]);
                b[j][1] = __float_as_uint(sW[n * 68 + k0 + 4 + lc]);
            }
            #pragma unroll
            for (int mt = 0; mt < 2; mt++)
                #pragma unroll
                for (int j = 0; j < NF; j++)
                    mma_tf32(cc[mt][j], a[mt], b[j]);
        }

        // ---- epilogue for this pass ----
        #pragma unroll
        for (int mt = 0; mt < 2; mt++) {
            #pragma unroll
            for (int j = 0; j < NF; j++) {
                int col = nh * 64 + warpN * NPW + j * 8 + lc2;
                #pragma unroll
                for (int half = 0; half < 2; half++) {
                    int r = row0 + warpM * 32 + mt * 16 + lr + half * 8;
                    if (r >= NN) continue;
                    float v0 = cc[mt][j][half * 2 + 0];
                    float v1 = cc[mt][j][half * 2 + 1];
                    if (EPI == 0) {
                        ((float2*)O0)[(r * CO + col) >> 1] = make_float2(v0, v1);
                    } else { // EPI == 2
                        if (col < 64) {
                            *(unsigned*)&((__half*)O0)[r * 64 + col] =
                                f2h2c(v0 * ASC, v1 * ASC);
                        } else {
                            int sc = col - 64;
                            ((float2*)O1)[(r * 64 + sc) >> 1] =
                                make_float2(v0 + bias[sc], v1 + bias[sc + 1]);
                        }
                    }
                }
            }
        }
        if (nh + 1 < NPASS) __syncthreads();
    }
}

// ---------------- standalone edge aggregation (fp16 asrc in, fp32 S out) ----------------
__global__ void __launch_bounds__(256) k_agg(const float* __restrict__ wd) {
    int gt = blockIdx.x * 256 + threadIdx.x;
    int n = gt >> 5, lane = gt & 31;
    if (n >= NN) return;
    const __half2* asrc2 = (const __half2*)g_asrc;
    float2 ad = ((const float2*)g_adst)[n * 32 + lane];
    float2 wdv = ((const float2*)wd)[lane];
    ad.x *= ASC; ad.y *= ASC;
    wdv.x *= ASC; wdv.y *= ASC;
    float ax = 0.f, ay = 0.f;
    int e0 = g_rowptr[n], e1 = g_rowptr[n + 1];
    int e = e0;
    while (e < e1) {
        int cnt = e1 - e; if (cnt > 8) cnt = 8;
        int sa[8]; float da[8];
        #pragma unroll
        for (int j = 0; j < 8; j++) if (j < cnt) { sa[j] = g_srcs[e + j]; da[j] = g_d2s[e + j]; }
        #pragma unroll
        for (int j = 0; j < 8; j++) if (j < cnt) {
            float2 af = __half22float2(asrc2[sa[j] * 32 + lane]);
            float px = af.x + ad.x + da[j] * wdv.x;
            float py = af.y + ad.y + da[j] * wdv.y;
            ax += fmaxf(px, 0.f); ay += fmaxf(py, 0.f);
        }
        e += cnt;
    }
    ((float2*)g_S)[n * 32 + lane] = make_float2(ax * ASCI, ay * ASCI);
}

// ---------------- fused node-update + next projection (K-split phase1, N-split phase2) ----------------
// W (g_W3M) and W2 must be tf32-prerounded.
// Phase 1: hnew = h + relu([h|S] @ W3M + deg*c2 + b3)  (two K=64 passes over shared A buffer)
// Phase 2 (MODE 0): [asrc|adst] = hnew @ [W1a|W1b] (+b1)   (two 64-col passes)
// Phase 2 (MODE 1): hio = relu(hnew) @ W2                  (one pass)
// Phase 2 (MODE 2): yO = relu(hnew) @ W2 + bias2           (one 32-col pass)
template<int CO2, int MODE>
__global__ void __launch_bounds__(256, 3) k_updproj(
    const float* __restrict__ W, const float* __restrict__ c2v,
    const float* __restrict__ b3v, const float* __restrict__ W2,
    const float* __restrict__ bias2, float* __restrict__ hio,
    __half* __restrict__ asrcO, float* __restrict__ adstO,
    float* __restrict__ yO)
{
    extern __shared__ float sm[];
    float* sA = sm;             // 128 x 68
    float* sW = sm + 128 * 68;  // 64 x 68 n-major
    const int tid = threadIdx.x;
    const int lane = tid & 31;
    const int wid = tid >> 5;
    const int warpM = wid & 3;
    const int warpN = wid >> 2;
    const int row0 = blockIdx.x * 128;
    const int lr = lane >> 2, lc = lane & 3, lc2 = (lane & 3) * 2;

    float cc[2][4][4];
    #pragma unroll
    for (int mt = 0; mt < 2; mt++)
        #pragma unroll
        for (int j = 0; j < 4; j++)
            cc[mt][j][0] = cc[mt][j][1] = cc[mt][j][2] = cc[mt][j][3] = 0.f;

    // ---- phase-1: two K=64 passes (kp=0: h, kp=1: S) ----
    #pragma unroll
    for (int kp = 0; kp < 2; kp++) {
        const float* Asrc = (kp == 0) ? hio : (const float*)g_S;
        #pragma unroll
        for (int i = 0; i < 8; i++) {
            int idx = tid + i * 256;
            int r = idx >> 4, c4 = idx & 15, gr = row0 + r;
            float4 v = make_float4(0.f, 0.f, 0.f, 0.f);
            if (gr < NN) v = ((const float4*)Asrc)[gr * 16 + c4];
            uint4 u = make_uint4(f2tf(v.x), f2tf(v.y), f2tf(v.z), f2tf(v.w));
            *(uint4*)&sA[r * 68 + c4 * 4] = u;
        }
        #pragma unroll
        for (int i = 0; i < 16; i++) {
            int idx = tid + i * 256;
            int kk = idx >> 6, c = idx & 63;
            sW[c * 68 + kk] = W[(kp * 64 + kk) * 64 + c];
        }
        __syncthreads();

        #pragma unroll
        for (int k0 = 0; k0 < 64; k0 += 8) {
            unsigned a[2][4];
            #pragma unroll
            for (int mt = 0; mt < 2; mt++) {
                int r = warpM * 32 + mt * 16 + lr;
                a[mt][0] = __float_as_uint(sA[r * 68 + k0 + lc]);
                a[mt][1] = __float_as_uint(sA[(r + 8) * 68 + k0 + lc]);
                a[mt][2] = __float_as_uint(sA[r * 68 + k0 + lc + 4]);
                a[mt][3] = __float_as_uint(sA[(r + 8) * 68 + k0 + lc + 4]);
            }
            unsigned b[4][2];
            #pragma unroll
            for (int j = 0; j < 4; j++) {
                int n = warpN * 32 + j * 8 + lr;
                b[j][0] = __float_as_uint(sW[n * 68 + k0 + lc]);
                b[j][1] = __float_as_uint(sW[n * 68 + k0 + 4 + lc]);
            }
            #pragma unroll
            for (int mt = 0; mt < 2; mt++)
                #pragma unroll
                for (int j = 0; j < 4; j++)
                    mma_tf32(cc[mt][j], a[mt], b[j]);
        }
        __syncthreads();
    }

    // ---- preload phase-2 W pass 0 (sW free) ----
    constexpr int NPASS2 = (CO2 + 63) / 64;
    constexpr int CW2 = (CO2 < 64) ? CO2 : 64;
    constexpr int NPW2 = CW2 / 2;
    constexpr int NF2 = NPW2 / 8;
    #pragma unroll
    for (int i = 0; i < (CW2 * 64) / 256; i++) {
        int idx = tid + i * 256;
        int kk = idx / CW2, c = idx % CW2;
        float w;
        if (MODE == 0) w = W2[kk * 64 + c];          // pass 0 = W1a
        else           w = W2[kk * CO2 + c];
        sW[c * 68 + kk] = w;
    }

    // ---- phase-1 epilogue: hnew -> (global h for MODE0) + sA cols 0-63 ----
    #pragma unroll
    for (int mt = 0; mt < 2; mt++) {
        #pragma unroll
        for (int j = 0; j < 4; j++) {
            int col = warpN * 32 + j * 8 + lc2;
            #pragma unroll
            for (int half = 0; half < 2; half++) {
                int rl = warpM * 32 + mt * 16 + lr + half * 8;
                int r = row0 + rl;
                if (r >= NN) continue;   // rows >= NN keep zeros (S pass zeroed them)
                float v0 = cc[mt][j][half * 2 + 0];
                float v1 = cc[mt][j][half * 2 + 1];
                float2 hv = ((const float2*)hio)[(r * 64 + col) >> 1];
                float dg = (float)g_deg[r];
                float o0 = hv.x + fmaxf(v0 + dg * c2v[col] + b3v[col], 0.f);
                float o1 = hv.y + fmaxf(v1 + dg * c2v[col + 1] + b3v[col + 1], 0.f);
                if (MODE == 0)
                    ((float2*)hio)[(r * 64 + col) >> 1] = make_float2(o0, o1);
                float a0 = (MODE != 0) ? fmaxf(o0, 0.f) : o0;
                float a1 = (MODE != 0) ? fmaxf(o1, 0.f) : o1;
                sA[rl * 68 + col]     = __uint_as_float(f2tf(a0));
                sA[rl * 68 + col + 1] = __uint_as_float(f2tf(a1));
            }
        }
    }
    __syncthreads();

    // ---- phase-2: N passes ----
    #pragma unroll
    for (int nh = 0; nh < NPASS2; nh++) {
        if (nh > 0) {
            __syncthreads();
            #pragma unroll
            for (int i = 0; i < (CW2 * 64) / 256; i++) {
                int idx = tid + i * 256;
                int kk = idx / CW2, c = idx % CW2;
                sW[c * 68 + kk] = W2[(64 + kk) * 64 + c];  // pass 1 = W1b
            }
            __syncthreads();
        }

        float dd[2][NF2][4];
        #pragma unroll
        for (int mt = 0; mt < 2; mt++)
            #pragma unroll
            for (int j = 0; j < NF2; j++)
                dd[mt][j][0] = dd[mt][j][1] = dd[mt][j][2] = dd[mt][j][3] = 0.f;

        #pragma unroll
        for (int k0 = 0; k0 < 64; k0 += 8) {
            unsigned a[2][4];
            #pragma unroll
            for (int mt = 0; mt < 2; mt++) {
                int r = warpM * 32 + mt * 16 + lr;
                a[mt][0] = __float_as_uint(sA[r * 68 + k0 + lc]);
                a[mt][1] = __float_as_uint(sA[(r + 8) * 68 + k0 + lc]);
                a[mt][2] = __float_as_uint(sA[r * 68 + k0 + lc + 4]);
                a[mt][3] = __float_as_uint(sA[(r + 8) * 68 + k0 + lc + 4]);
            }
            unsigned b[NF2][2];
            #pragma unroll
            for (int j = 0; j < NF2; j++) {
                int n = warpN * NPW2 + j * 8 + lr;
                b[j][0] = __float_as_uint(sW[n * 68 + k0 + lc]);
                b[j][1] = __float_as_uint(sW[n * 68 + k0 + 4 + lc]);
            }
            #pragma unroll
            for (int mt = 0; mt < 2; mt++)
                #pragma unroll
                for (int j = 0; j < NF2; j++)
                    mma_tf32(dd[mt][j], a[mt], b[j]);
        }

        #pragma unroll
        for (int mt = 0; mt < 2; mt++) {
            #pragma unroll
            for (int j = 0; j < NF2; j++) {
                int col = nh * 64 + warpN * NPW2 + j * 8 + lc2;
                #pragma unroll
                for (int half = 0; half < 2; half++) {
                    int r = row0 + warpM * 32 + mt * 16 + lr + half * 8;
                    if (r >= NN) continue;
                    float v0 = dd[mt][j][half * 2 + 0];
                    float v1 = dd[mt][j][half * 2 + 1];
                    if (MODE == 0) {
                        if (col < 64) {
                            *(unsigned*)&asrcO[r * 64 + col] = f2h2c(v0 * ASC, v1 * ASC);
                        } else {
                            int sc = col - 64;
                            ((float2*)adstO)[(r * 64 + sc) >> 1] =
                                make_float2(v0 + bias2[sc], v1 + bias2[sc + 1]);
                        }
                    } else if (MODE == 1) {
                        ((float2*)hio)[(r * 64 + col) >> 1] = make_float2(v0, v1);
                    } else {
                        ((float2*)yO)[(r * 32 + col) >> 1] =
                            make_float2(v0 + bias2[col], v1 + bias2[col + 1]);
                    }
                }
            }
        }
    }
}

// ---------------- pooling ----------------
__global__ void k_pool_acc(const int* __restrict__ batch) {
    int gt = blockIdx.x * 256 + threadIdx.x;
    int w = gt >> 5, lane = gt & 31;
    const int TW = 64 * 8;
    const int STRIP = (NN + TW - 1) / TW;
    int n0 = w * STRIP;
    if (n0 >= NN) return;
    int n1 = n0 + STRIP; if (n1 > NN) n1 = NN;
    int cur = batch[n0]; float acc = 0.f;
    for (int n = n0; n < n1; n++) {
        int g = batch[n];
        float v = g_y[n * 32 + lane];
        if (g != cur) { atomicAdd(&g_pool[cur * 32 + lane], acc); acc = 0.f; cur = g; }
        acc += v;
    }
    atomicAdd(&g_pool[cur * 32 + lane], acc);
}

__global__ void k_pool_fin(const int* __restrict__ batch, float* __restrict__ out) {
    int i = blockIdx.x * 256 + threadIdx.x;
    if (i >= GG * 32) return;
    int g = i >> 5;
    int lo = 0, hi = NN;
    while (lo < hi) { int mid = (lo + hi) >> 1; if (batch[mid] < g) lo = mid + 1; else hi = mid; }
    int a = lo;
    lo = 0; hi = NN;
    while (lo < hi) { int mid = (lo + hi) >> 1; if (batch[mid] < g + 1) lo = mid + 1; else hi = mid; }
    int cnt = lo - a;
    out[i] = g_pool[i] / fmaxf((float)cnt, 1.f);
}

// ---------------- launch ----------------
extern "C" void kernel_launch(void* const* d_in, const int* in_sizes, int n_in,
                              void* d_out, int out_size) {
    const float* pos    = (const float*)d_in[0];
    const int*   z      = (const int*)d_in[1];
    const int*   ei     = (const int*)d_in[2];
    const int*   batch  = (const int*)d_in[3];
    const float* emb    = (const float*)d_in[4];
    const float* t1_Win = (const float*)d_in[5];
    const float* t1_W1  = (const float*)d_in[6];
    const float* t1_b1  = (const float*)d_in[7];
    const float* t1_W2  = (const float*)d_in[8];
    const float* t1_b2  = (const float*)d_in[9];
    const float* t1_W3  = (const float*)d_in[10];
    const float* t1_b3  = (const float*)d_in[11];
    const float* t2_Win = (const float*)d_in[12];
    const float* t2_W1  = (const float*)d_in[13];
    const float* t2_b1  = (const float*)d_in[14];
    const float* t2_W2  = (const float*)d_in[15];
    const float* t2_b2  = (const float*)d_in[16];
    const float* t2_W3  = (const float*)d_in[17];
    const float* t2_b3  = (const float*)d_in[18];
    const float* Wlin   = (const float*)d_in[19];
    const float* blin   = (const float*)d_in[20];
    float* out = (float*)d_out;

    float *ph, *pad, *py, *pW3M, *pc2, *pWc;
    __half* pash;
    cudaGetSymbolAddress((void**)&ph, g_h);
    cudaGetSymbolAddress((void**)&pash, g_asrc);
    cudaGetSymbolAddress((void**)&pad, g_adst);
    cudaGetSymbolAddress((void**)&py, g_y);
    cudaGetSymbolAddress((void**)&pW3M, g_W3M);
    cudaGetSymbolAddress((void**)&pc2, g_c2);
    cudaGetSymbolAddress((void**)&pWc, g_Wc);

    const int NB = (NN + 127) / 128;
    const int nscan = (NN + 1023) / 1024;
    const int SM_T = (128 * 68 + 64 * 68) * 4;   // 52224 for all GEMM kernels

    cudaFuncSetAttribute(k_mma<64, 2, 0>,   cudaFuncAttributeMaxDynamicSharedMemorySize, SM_T);
    cudaFuncSetAttribute(k_mma<128, 0, 2>,  cudaFuncAttributeMaxDynamicSharedMemorySize, SM_T);
    cudaFuncSetAttribute(k_updproj<128, 0>, cudaFuncAttributeMaxDynamicSharedMemorySize, SM_T);
    cudaFuncSetAttribute(k_updproj<64, 1>,  cudaFuncAttributeMaxDynamicSharedMemorySize, SM_T);
    cudaFuncSetAttribute(k_updproj<32, 2>,  cudaFuncAttributeMaxDynamicSharedMemorySize, SM_T);

    // pre-rounded weight views
    const float* cW1t1  = pWc;                 // t1 W1 (4 layers x 129x64)
    const float* cW1t2  = pWc + 33024;         // t2 W1
    const float* cWin2  = pWc + 66048;         // t2_Win 64x64
    const float* cWlin  = pWc + 70144;         // Wlin 64x32
    const float* cWin1  = pWc + 72192;         // t1_Win 64x64

    // setup (proj stays launch #6 for ncu)
    k_zero<<<(NN + 255) / 256, 256>>>();
    k_d2deg<<<(EE + 255) / 256, 256>>>(pos, ei);
    k_prepW<<<(76288 + 255) / 256, 256>>>(t1_W1, t2_W1, t2_Win, Wlin, t1_Win);
    // features + input projection  h = [pos|emb[z]] @ t1_Win
    k_mma<64, 2, 0><<<NB, 256, SM_T>>>(
        nullptr, cWin1, nullptr, ph, nullptr, pos, z, emb);
    k_scan1<<<nscan, 256>>>();
    // t1 layer-0 projection (profiled launch)
    k_mma<128, 0, 2><<<NB, 256, SM_T>>>(
        ph, cW1t1, t1_b1, (float*)pash, pad, nullptr, nullptr, nullptr);
    // CSR build + weight prep
    k_scan2<<<1, 128>>>(nscan);
    k_scan3<<<nscan, 1024>>>();
    k_scatter<<<(EE + 255) / 256, 256>>>(ei);
    k_prepM<<<8, 256>>>(t1_W2, t1_W3, t1_b2, t2_W2, t2_W3, t2_b2);

    for (int t = 0; t < 2; t++) {
        const float* W1raw = (t == 0 ? t1_W1 : t2_W1);     // agg wd column (fp32)
        const float* cW1   = (t == 0 ? cW1t1 : cW1t2);
        const float* b1 = (t == 0 ? t1_b1 : t2_b1);
        const float* b3 = (t == 0 ? t1_b3 : t2_b3);
        for (int l = 0; l < 4; l++) {
            k_agg<<<(NN * 32 + 255) / 256, 256>>>(W1raw + l * 129 * 64 + 128 * 64);
            const float* Wu = pW3M + (t * 4 + l) * 8192;
            const float* cu = pc2 + (t * 4 + l) * 64;
            if (l < 3) {
                k_updproj<128, 0><<<NB, 256, SM_T>>>(
                    Wu, cu, b3 + l * 64, cW1 + (l + 1) * 129 * 64, b1 + (l + 1) * 64,
                    ph, pash, pad, nullptr);
            } else if (t == 0) {
                k_updproj<64, 1><<<NB, 256, SM_T>>>(
                    Wu, cu, b3 + l * 64, cWin2, nullptr,
                    ph, nullptr, nullptr, nullptr);
            } else {
                k_updproj<32, 2><<<NB, 256, SM_T>>>(
                    Wu, cu, b3 + l * 64, cWlin, blin,
                    ph, nullptr, nullptr, py);
            }
        }
        if (t == 0) {
            k_mma<128, 0, 2><<<NB, 256, SM_T>>>(
                ph, cW1t2, t2_b1, (float*)pash, pad, nullptr, nullptr, nullptr);
        }
    }
    k_pool_acc<<<64, 256>>>(batch);
    k_pool_fin<<<(GG * 32 + 255) / 256, 256>>>(batch, out);
}